// round 10
// baseline (speedup 1.0000x reference)
#include <cuda_runtime.h>
#include <cuda_bf16.h>
#include <cuda_fp8.h>
#include <cstdint>

// Shapes fixed by dataset: M=16384, K=4096, N=4096
__device__ uint8_t g_qx[67108864];   // 16384*4096 bytes
__device__ uint8_t g_qw[16777216];   // 4096*4096 bytes
__device__ unsigned int g_amax_bits;

static __device__ __forceinline__ uint32_t smem_u32(const void* p) {
    return (uint32_t)__cvta_generic_to_shared(p);
}

// ---------------------------------------------------------------------------
// 1) amax reduction
// ---------------------------------------------------------------------------
__global__ void init_amax_kernel() { g_amax_bits = 0u; }

__global__ void amax_kernel(const float* __restrict__ x, int n4) {
    const float4* x4 = (const float4*)x;
    float m = 0.0f;
    for (int i = blockIdx.x * blockDim.x + threadIdx.x; i < n4;
         i += gridDim.x * blockDim.x) {
        float4 v = __ldcs(&x4[i]);
        m = fmaxf(m, fabsf(v.x)); m = fmaxf(m, fabsf(v.y));
        m = fmaxf(m, fabsf(v.z)); m = fmaxf(m, fabsf(v.w));
    }
#pragma unroll
    for (int o = 16; o > 0; o >>= 1)
        m = fmaxf(m, __shfl_xor_sync(0xffffffffu, m, o));
    if ((threadIdx.x & 31) == 0)
        atomicMax(&g_amax_bits, __float_as_uint(m)); // m >= 0
}

// ---------------------------------------------------------------------------
// 2) one pass: quantize x -> e4m3 bytes AND convert w -> e4m3 bytes
// ---------------------------------------------------------------------------
__global__ void quantize_both_kernel(const float* __restrict__ x,
                                     const float* __restrict__ w,
                                     int nx4, int nw4) {
    float amax = fmaxf(__uint_as_float(g_amax_bits), 1e-12f);
    float s = 448.0f / amax;
    const int total = nx4 + nw4;
    for (int i = blockIdx.x * blockDim.x + threadIdx.x; i < total;
         i += gridDim.x * blockDim.x) {
        if (i < nx4) {
            float4 v = __ldcs(&((const float4*)x)[i]);
            uchar4 o;
            o.x = __nv_fp8_e4m3(v.x * s).__x;
            o.y = __nv_fp8_e4m3(v.y * s).__x;
            o.z = __nv_fp8_e4m3(v.z * s).__x;
            o.w = __nv_fp8_e4m3(v.w * s).__x;
            ((uchar4*)g_qx)[i] = o;
        } else {
            int j = i - nx4;
            float4 v = __ldcs(&((const float4*)w)[j]);
            uchar4 o;   // w already holds exact e4m3 values -> conversion exact
            o.x = __nv_fp8_e4m3(v.x).__x;
            o.y = __nv_fp8_e4m3(v.y).__x;
            o.z = __nv_fp8_e4m3(v.z).__x;
            o.w = __nv_fp8_e4m3(v.w).__x;
            ((uchar4*)g_qw)[j] = o;
        }
    }
}

// ---------------------------------------------------------------------------
// 3) fp8 GEMM via mma.sync m16n8k32 e4m3:
//    CTA tile 128x256, 8 warps (2x4), warp tile 64x64, 1 CTA/SM.
//    BK=128 bytes/chunk, 3-stage cp.async pipeline.
// ---------------------------------------------------------------------------
#define BM 128
#define BN 256
#define BKB 128                 // K bytes per chunk (= 4 x k32)
#define STAGES 3
#define RSTR 144                // padded smem row stride (16B aligned)
#define A_STAGE (BM * RSTR)     // 18432
#define B_STAGE (BN * RSTR)     // 36864
#define STAGE_BYTES (A_STAGE + B_STAGE)   // 55296
#define SMEM_TOTAL (STAGES * STAGE_BYTES) // 165888

static __device__ __forceinline__ void cp16(uint32_t dst, const void* src) {
    asm volatile("cp.async.cg.shared.global [%0], [%1], 16;"
                 :: "r"(dst), "l"(src) : "memory");
}

static __device__ __forceinline__ void load_stage(
    uint32_t sbase, int stage, const uint8_t* A, const uint8_t* B,
    int bm, int bn, int k0, int K, int tid) {
    uint32_t abase = sbase + stage * STAGE_BYTES;
    uint32_t bbase = abase + A_STAGE;
    // A: 128 rows x 8 vec16 = 1024 -> 4/thread
#pragma unroll
    for (int i = 0; i < 4; i++) {
        int id = i * 256 + tid;
        int row = id >> 3, c16 = (id & 7) * 16;
        cp16(abase + row * RSTR + c16, A + (size_t)(bm + row) * K + k0 + c16);
    }
    // B: 256 rows x 8 vec16 = 2048 -> 8/thread
#pragma unroll
    for (int i = 0; i < 8; i++) {
        int id = i * 256 + tid;
        int row = id >> 3, c16 = (id & 7) * 16;
        cp16(bbase + row * RSTR + c16, B + (size_t)(bn + row) * K + k0 + c16);
    }
}

__global__ __launch_bounds__(256, 1)
void gemm_kernel(const float* __restrict__ bias,
                 const float* __restrict__ w_scale,
                 float* __restrict__ C, int M, int N, int K) {
    extern __shared__ char smem[];
    const uint32_t sbase = smem_u32(smem);
    const int tid  = threadIdx.x;
    const int warp = tid >> 5;
    const int lane = tid & 31;
    const int wm   = warp >> 2;   // 0..1: 64-row warp tile
    const int wn   = warp & 3;    // 0..3: 64-col warp tile
    const int bm   = blockIdx.y * BM;
    const int bn   = blockIdx.x * BN;
    const int NCHUNK = K / BKB;   // 32

    const uint8_t* A = g_qx;
    const uint8_t* B = g_qw;

    float acc[4][8][4];
#pragma unroll
    for (int a = 0; a < 4; a++)
#pragma unroll
        for (int b = 0; b < 8; b++)
#pragma unroll
            for (int c = 0; c < 4; c++) acc[a][b][c] = 0.0f;

    // prologue: stages 0,1
#pragma unroll
    for (int c = 0; c < STAGES - 1; c++) {
        load_stage(sbase, c, A, B, bm, bn, c * BKB, K, tid);
        asm volatile("cp.async.commit_group;" ::: "memory");
    }

    for (int c = 0; c < NCHUNK; c++) {
        asm volatile("cp.async.wait_group %0;" :: "n"(STAGES - 2) : "memory");
        __syncthreads();

        // issue loads for chunk c+2 into stage (c+2)%3 (stage of chunk c-1,
        // whose compute finished before the barrier above)
        if (c + STAGES - 1 < NCHUNK)
            load_stage(sbase, (c + STAGES - 1) % STAGES, A, B, bm, bn,
                       (c + STAGES - 1) * BKB, K, tid);
        asm volatile("cp.async.commit_group;" ::: "memory");

        const uint32_t abase = sbase + (c % STAGES) * STAGE_BYTES;
        const uint32_t bbase = abase + A_STAGE;

#pragma unroll
        for (int ks = 0; ks < 4; ks++) {      // four k32 steps per 128B chunk
            const int kb = ks * 32;           // byte offset within row
            uint32_t af[4][4];
            uint32_t bf[8][2];
#pragma unroll
            for (int mt = 0; mt < 4; mt++) {
                int row = wm * 64 + mt * 16 + (lane & 15);
                int col = kb + (lane >> 4) * 16;
                uint32_t addr = abase + row * RSTR + col;
                asm volatile(
                    "ldmatrix.sync.aligned.m8n8.x4.shared.b16 {%0,%1,%2,%3}, [%4];"
                    : "=r"(af[mt][0]), "=r"(af[mt][1]),
                      "=r"(af[mt][2]), "=r"(af[mt][3])
                    : "r"(addr));
            }
#pragma unroll
            for (int p = 0; p < 4; p++) {
                int row = wn * 64 + p * 16 + ((lane >> 4) << 3) + (lane & 7);
                int col = kb + ((lane >> 3) & 1) * 16;
                uint32_t addr = bbase + row * RSTR + col;
                uint32_t r0, r1, r2, r3;
                asm volatile(
                    "ldmatrix.sync.aligned.m8n8.x4.shared.b16 {%0,%1,%2,%3}, [%4];"
                    : "=r"(r0), "=r"(r1), "=r"(r2), "=r"(r3)
                    : "r"(addr));
                bf[2 * p + 0][0] = r0; bf[2 * p + 0][1] = r1;
                bf[2 * p + 1][0] = r2; bf[2 * p + 1][1] = r3;
            }
#pragma unroll
            for (int mt = 0; mt < 4; mt++) {
#pragma unroll
                for (int nt = 0; nt < 8; nt++) {
                    asm("mma.sync.aligned.m16n8k32.row.col.f32.e4m3.e4m3.f32 "
                        "{%0,%1,%2,%3}, {%4,%5,%6,%7}, {%8,%9}, {%0,%1,%2,%3};"
                        : "+f"(acc[mt][nt][0]), "+f"(acc[mt][nt][1]),
                          "+f"(acc[mt][nt][2]), "+f"(acc[mt][nt][3])
                        : "r"(af[mt][0]), "r"(af[mt][1]),
                          "r"(af[mt][2]), "r"(af[mt][3]),
                          "r"(bf[nt][0]), "r"(bf[nt][1]));
                }
            }
        }
    }

    // epilogue: out = acc * (x_scale * w_scale) + bias
    float amax = fmaxf(__uint_as_float(g_amax_bits), 1e-12f);
    float sq = 448.0f / amax;
    float total = (1.0f / sq) * __ldg(w_scale);

#pragma unroll
    for (int mt = 0; mt < 4; mt++) {
        int r0 = bm + wm * 64 + mt * 16 + (lane >> 2);
#pragma unroll
        for (int nt = 0; nt < 8; nt++) {
            int cix = bn + wn * 64 + nt * 8 + (lane & 3) * 2;
            float b0 = __ldg(&bias[cix]);
            float b1 = __ldg(&bias[cix + 1]);
            float2 v0, v1;
            v0.x = acc[mt][nt][0] * total + b0;
            v0.y = acc[mt][nt][1] * total + b1;
            v1.x = acc[mt][nt][2] * total + b0;
            v1.y = acc[mt][nt][3] * total + b1;
            *(float2*)(C + (size_t)r0 * N + cix)       = v0;
            *(float2*)(C + (size_t)(r0 + 8) * N + cix) = v1;
        }
    }
}

// ---------------------------------------------------------------------------
extern "C" void kernel_launch(void* const* d_in, const int* in_sizes, int n_in,
                              void* d_out, int out_size) {
    const float* x       = (const float*)d_in[0];
    const float* w       = (const float*)d_in[1];
    const float* w_scale = (const float*)d_in[2];
    const float* bias    = (const float*)d_in[3];
    float* out           = (float*)d_out;

    int N = in_sizes[3];
    int K = in_sizes[1] / N;
    int M = in_sizes[0] / K;
    int nx4 = (M * K) / 4;
    int nw4 = (N * K) / 4;

    cudaFuncSetAttribute(gemm_kernel,
                         cudaFuncAttributeMaxDynamicSharedMemorySize, SMEM_TOTAL);

    init_amax_kernel<<<1, 1>>>();
    amax_kernel<<<2960, 256>>>(x, nx4);                 // 20 x 148
    quantize_both_kernel<<<3552, 256>>>(x, w, nx4, nw4); // 24 x 148

    dim3 grid(N / BN, M / BM);
    gemm_kernel<<<grid, 256, SMEM_TOTAL>>>(bias, w_scale, out, M, N, K);
}

// round 11
// speedup vs baseline: 1.0055x; 1.0055x over previous
#include <cuda_runtime.h>
#include <cuda_bf16.h>
#include <cuda_fp8.h>
#include <cstdint>

// Shapes fixed by dataset: M=16384, K=4096, N=4096
__device__ uint8_t g_qx[67108864];   // 16384*4096 bytes
__device__ uint8_t g_qw[16777216];   // 4096*4096 bytes
__device__ unsigned int g_amax_bits;

static __device__ __forceinline__ uint32_t smem_u32(const void* p) {
    return (uint32_t)__cvta_generic_to_shared(p);
}

// ---------------------------------------------------------------------------
// 1) amax reduction
// ---------------------------------------------------------------------------
__global__ void init_amax_kernel() { g_amax_bits = 0u; }

__global__ void amax_kernel(const float* __restrict__ x, int n4) {
    const float4* x4 = (const float4*)x;
    float m = 0.0f;
    for (int i = blockIdx.x * blockDim.x + threadIdx.x; i < n4;
         i += gridDim.x * blockDim.x) {
        float4 v = __ldcs(&x4[i]);
        m = fmaxf(m, fabsf(v.x)); m = fmaxf(m, fabsf(v.y));
        m = fmaxf(m, fabsf(v.z)); m = fmaxf(m, fabsf(v.w));
    }
#pragma unroll
    for (int o = 16; o > 0; o >>= 1)
        m = fmaxf(m, __shfl_xor_sync(0xffffffffu, m, o));
    if ((threadIdx.x & 31) == 0)
        atomicMax(&g_amax_bits, __float_as_uint(m)); // m >= 0
}

// ---------------------------------------------------------------------------
// 2) one pass: quantize x -> e4m3 bytes AND convert w -> e4m3 bytes
// ---------------------------------------------------------------------------
__global__ void quantize_both_kernel(const float* __restrict__ x,
                                     const float* __restrict__ w,
                                     int nx4, int nw4) {
    float amax = fmaxf(__uint_as_float(g_amax_bits), 1e-12f);
    float s = 448.0f / amax;
    const int total = nx4 + nw4;
    for (int i = blockIdx.x * blockDim.x + threadIdx.x; i < total;
         i += gridDim.x * blockDim.x) {
        if (i < nx4) {
            float4 v = __ldcs(&((const float4*)x)[i]);
            uchar4 o;
            o.x = __nv_fp8_e4m3(v.x * s).__x;
            o.y = __nv_fp8_e4m3(v.y * s).__x;
            o.z = __nv_fp8_e4m3(v.z * s).__x;
            o.w = __nv_fp8_e4m3(v.w * s).__x;
            ((uchar4*)g_qx)[i] = o;
        } else {
            int j = i - nx4;
            float4 v = __ldcs(&((const float4*)w)[j]);
            uchar4 o;   // w already holds exact e4m3 values -> conversion exact
            o.x = __nv_fp8_e4m3(v.x).__x;
            o.y = __nv_fp8_e4m3(v.y).__x;
            o.z = __nv_fp8_e4m3(v.z).__x;
            o.w = __nv_fp8_e4m3(v.w).__x;
            ((uchar4*)g_qw)[j] = o;
        }
    }
}

// ---------------------------------------------------------------------------
// 3) fp8 GEMM via mma.sync m16n8k32 e4m3:
//    128x128 CTA tile, 8 warps (4x2), warp tile 32x64, 2 CTAs/SM.
//    BK=128 bytes/chunk, 3-stage cp.async pipeline (32 barriers/CTA).
// ---------------------------------------------------------------------------
#define BM 128
#define BN 128
#define BKB 128                 // K bytes per chunk (= 4 x k32)
#define STAGES 3
#define RSTR 144                // padded smem row stride (16B aligned)
#define A_STAGE (BM * RSTR)     // 18432
#define B_STAGE (BN * RSTR)     // 18432
#define STAGE_BYTES (A_STAGE + B_STAGE)   // 36864
#define SMEM_TOTAL (STAGES * STAGE_BYTES) // 110592 (x2 CTAs = 221184 <= 228KB)

static __device__ __forceinline__ void cp16(uint32_t dst, const void* src) {
    asm volatile("cp.async.cg.shared.global [%0], [%1], 16;"
                 :: "r"(dst), "l"(src) : "memory");
}

static __device__ __forceinline__ void load_stage(
    uint32_t sbase, int stage, const uint8_t* A, const uint8_t* B,
    int bm, int bn, int k0, int K, int tid) {
    uint32_t abase = sbase + stage * STAGE_BYTES;
    uint32_t bbase = abase + A_STAGE;
    // A and B: 128 rows x 8 vec16 = 1024 vecs each -> 4/thread each
#pragma unroll
    for (int i = 0; i < 4; i++) {
        int id = i * 256 + tid;
        int row = id >> 3, c16 = (id & 7) * 16;
        cp16(abase + row * RSTR + c16, A + (size_t)(bm + row) * K + k0 + c16);
    }
#pragma unroll
    for (int i = 0; i < 4; i++) {
        int id = i * 256 + tid;
        int row = id >> 3, c16 = (id & 7) * 16;
        cp16(bbase + row * RSTR + c16, B + (size_t)(bn + row) * K + k0 + c16);
    }
}

static __device__ __forceinline__ void load_frags(
    uint32_t abase, uint32_t bbase, int wm, int wn, int lane, int kb,
    uint32_t (&af)[2][4], uint32_t (&bf)[8][2]) {
#pragma unroll
    for (int mt = 0; mt < 2; mt++) {
        int row = wm * 32 + mt * 16 + (lane & 15);
        int col = kb + (lane >> 4) * 16;
        uint32_t addr = abase + row * RSTR + col;
        asm volatile(
            "ldmatrix.sync.aligned.m8n8.x4.shared.b16 {%0,%1,%2,%3}, [%4];"
            : "=r"(af[mt][0]), "=r"(af[mt][1]), "=r"(af[mt][2]), "=r"(af[mt][3])
            : "r"(addr));
    }
#pragma unroll
    for (int p = 0; p < 4; p++) {
        int row = wn * 64 + p * 16 + ((lane >> 4) << 3) + (lane & 7);
        int col = kb + ((lane >> 3) & 1) * 16;
        uint32_t addr = bbase + row * RSTR + col;
        uint32_t r0, r1, r2, r3;
        asm volatile(
            "ldmatrix.sync.aligned.m8n8.x4.shared.b16 {%0,%1,%2,%3}, [%4];"
            : "=r"(r0), "=r"(r1), "=r"(r2), "=r"(r3)
            : "r"(addr));
        bf[2 * p + 0][0] = r0; bf[2 * p + 0][1] = r1;
        bf[2 * p + 1][0] = r2; bf[2 * p + 1][1] = r3;
    }
}

static __device__ __forceinline__ void do_mmas(
    float (&acc)[2][8][4], const uint32_t (&af)[2][4], const uint32_t (&bf)[8][2]) {
#pragma unroll
    for (int mt = 0; mt < 2; mt++) {
#pragma unroll
        for (int nt = 0; nt < 8; nt++) {
            asm("mma.sync.aligned.m16n8k32.row.col.f32.e4m3.e4m3.f32 "
                "{%0,%1,%2,%3}, {%4,%5,%6,%7}, {%8,%9}, {%0,%1,%2,%3};"
                : "+f"(acc[mt][nt][0]), "+f"(acc[mt][nt][1]),
                  "+f"(acc[mt][nt][2]), "+f"(acc[mt][nt][3])
                : "r"(af[mt][0]), "r"(af[mt][1]),
                  "r"(af[mt][2]), "r"(af[mt][3]),
                  "r"(bf[nt][0]), "r"(bf[nt][1]));
        }
    }
}

__global__ __launch_bounds__(256, 2)
void gemm_kernel(const float* __restrict__ bias,
                 const float* __restrict__ w_scale,
                 float* __restrict__ C, int M, int N, int K) {
    extern __shared__ char smem[];
    const uint32_t sbase = smem_u32(smem);
    const int tid  = threadIdx.x;
    const int warp = tid >> 5;
    const int lane = tid & 31;
    const int wm   = warp >> 1;   // 0..3: 32-row warp tile
    const int wn   = warp & 1;    // 0..1: 64-col warp tile
    const int bm   = blockIdx.y * BM;
    const int bn   = blockIdx.x * BN;
    const int NCHUNK = K / BKB;   // 32

    const uint8_t* A = g_qx;
    const uint8_t* B = g_qw;

    float acc[2][8][4];
#pragma unroll
    for (int a = 0; a < 2; a++)
#pragma unroll
        for (int b = 0; b < 8; b++)
#pragma unroll
            for (int c = 0; c < 4; c++) acc[a][b][c] = 0.0f;

    // prologue: stages 0,1
#pragma unroll
    for (int c = 0; c < STAGES - 1; c++) {
        load_stage(sbase, c, A, B, bm, bn, c * BKB, K, tid);
        asm volatile("cp.async.commit_group;" ::: "memory");
    }

    for (int c = 0; c < NCHUNK; c++) {
        asm volatile("cp.async.wait_group %0;" :: "n"(STAGES - 2) : "memory");
        __syncthreads();

        const uint32_t abase = sbase + (c % STAGES) * STAGE_BYTES;
        const uint32_t bbase = abase + A_STAGE;

        uint32_t af[2][4];
        uint32_t bf[8][2];

        // kstep 0 fragments first: their LDSM latency hides under the
        // cp.async issue burst for chunk c+2 below.
        load_frags(abase, bbase, wm, wn, lane, 0, af, bf);

        // issue loads for chunk c+2 into stage (c+2)%3 (stage of chunk c-1,
        // whose compute finished before the barrier above)
        if (c + STAGES - 1 < NCHUNK)
            load_stage(sbase, (c + STAGES - 1) % STAGES, A, B, bm, bn,
                       (c + STAGES - 1) * BKB, K, tid);
        asm volatile("cp.async.commit_group;" ::: "memory");

        do_mmas(acc, af, bf);
#pragma unroll
        for (int ks = 1; ks < 4; ks++) {
            load_frags(abase, bbase, wm, wn, lane, ks * 32, af, bf);
            do_mmas(acc, af, bf);
        }
    }

    // epilogue: out = acc * (x_scale * w_scale) + bias
    float amax = fmaxf(__uint_as_float(g_amax_bits), 1e-12f);
    float sq = 448.0f / amax;
    float total = (1.0f / sq) * __ldg(w_scale);

#pragma unroll
    for (int mt = 0; mt < 2; mt++) {
        int r0 = bm + wm * 32 + mt * 16 + (lane >> 2);
#pragma unroll
        for (int nt = 0; nt < 8; nt++) {
            int cix = bn + wn * 64 + nt * 8 + (lane & 3) * 2;
            float b0 = __ldg(&bias[cix]);
            float b1 = __ldg(&bias[cix + 1]);
            float2 v0, v1;
            v0.x = acc[mt][nt][0] * total + b0;
            v0.y = acc[mt][nt][1] * total + b1;
            v1.x = acc[mt][nt][2] * total + b0;
            v1.y = acc[mt][nt][3] * total + b1;
            *(float2*)(C + (size_t)r0 * N + cix)       = v0;
            *(float2*)(C + (size_t)(r0 + 8) * N + cix) = v1;
        }
    }
}

// ---------------------------------------------------------------------------
extern "C" void kernel_launch(void* const* d_in, const int* in_sizes, int n_in,
                              void* d_out, int out_size) {
    const float* x       = (const float*)d_in[0];
    const float* w       = (const float*)d_in[1];
    const float* w_scale = (const float*)d_in[2];
    const float* bias    = (const float*)d_in[3];
    float* out           = (float*)d_out;

    int N = in_sizes[3];
    int K = in_sizes[1] / N;
    int M = in_sizes[0] / K;
    int nx4 = (M * K) / 4;
    int nw4 = (N * K) / 4;

    cudaFuncSetAttribute(gemm_kernel,
                         cudaFuncAttributeMaxDynamicSharedMemorySize, SMEM_TOTAL);

    init_amax_kernel<<<1, 1>>>();
    amax_kernel<<<2960, 256>>>(x, nx4);                  // 20 x 148
    quantize_both_kernel<<<3552, 256>>>(x, w, nx4, nw4); // 24 x 148

    dim3 grid(N / BN, M / BM);
    gemm_kernel<<<grid, 256, SMEM_TOTAL>>>(bias, w_scale, out, M, N, K);
}

// round 12
// speedup vs baseline: 1.1401x; 1.1338x over previous
#include <cuda_runtime.h>
#include <cuda_bf16.h>
#include <cuda_fp8.h>
#include <cstdint>

// Shapes fixed by dataset: M=16384, K=4096, N=4096
__device__ uint8_t g_qx[67108864];   // 16384*4096 bytes
__device__ uint8_t g_qw[16777216];   // 4096*4096 bytes
__device__ unsigned int g_amax_bits;

static __device__ __forceinline__ uint32_t smem_u32(const void* p) {
    return (uint32_t)__cvta_generic_to_shared(p);
}

// ---------------------------------------------------------------------------
// 1) amax reduction
// ---------------------------------------------------------------------------
__global__ void init_amax_kernel() { g_amax_bits = 0u; }

__global__ void amax_kernel(const float* __restrict__ x, int n4) {
    const float4* x4 = (const float4*)x;
    float m = 0.0f;
    for (int i = blockIdx.x * blockDim.x + threadIdx.x; i < n4;
         i += gridDim.x * blockDim.x) {
        float4 v = __ldcs(&x4[i]);
        m = fmaxf(m, fabsf(v.x)); m = fmaxf(m, fabsf(v.y));
        m = fmaxf(m, fabsf(v.z)); m = fmaxf(m, fabsf(v.w));
    }
#pragma unroll
    for (int o = 16; o > 0; o >>= 1)
        m = fmaxf(m, __shfl_xor_sync(0xffffffffu, m, o));
    if ((threadIdx.x & 31) == 0)
        atomicMax(&g_amax_bits, __float_as_uint(m)); // m >= 0
}

// ---------------------------------------------------------------------------
// 2) one pass: quantize x -> e4m3 bytes AND convert w -> e4m3 bytes
// ---------------------------------------------------------------------------
__global__ void quantize_both_kernel(const float* __restrict__ x,
                                     const float* __restrict__ w,
                                     int nx4, int nw4) {
    float amax = fmaxf(__uint_as_float(g_amax_bits), 1e-12f);
    float s = 448.0f / amax;
    const int total = nx4 + nw4;
    for (int i = blockIdx.x * blockDim.x + threadIdx.x; i < total;
         i += gridDim.x * blockDim.x) {
        if (i < nx4) {
            float4 v = __ldcs(&((const float4*)x)[i]);
            uchar4 o;
            o.x = __nv_fp8_e4m3(v.x * s).__x;
            o.y = __nv_fp8_e4m3(v.y * s).__x;
            o.z = __nv_fp8_e4m3(v.z * s).__x;
            o.w = __nv_fp8_e4m3(v.w * s).__x;
            ((uchar4*)g_qx)[i] = o;
        } else {
            int j = i - nx4;
            float4 v = __ldcs(&((const float4*)w)[j]);
            uchar4 o;   // w already holds exact e4m3 values -> conversion exact
            o.x = __nv_fp8_e4m3(v.x).__x;
            o.y = __nv_fp8_e4m3(v.y).__x;
            o.z = __nv_fp8_e4m3(v.z).__x;
            o.w = __nv_fp8_e4m3(v.w).__x;
            ((uchar4*)g_qw)[j] = o;
        }
    }
}

// ---------------------------------------------------------------------------
// 3) fp8 GEMM via mma.sync m16n8k32 e4m3:
//    128x128 CTA tile, 8 warps (4x2), warp tile 32x64, 2 CTAs/SM.
//    BK=64 bytes/chunk, 4-stage cp.async pipeline.
//    Loop unrolled by STAGES: all smem addresses are base_reg + const-imm.
// ---------------------------------------------------------------------------
#define BM 128
#define BN 128
#define BKB 64                  // K bytes per chunk (= k64 in fp8)
#define STAGES 4
#define RSTR 80                 // padded smem row stride (16B aligned)
#define A_STAGE (BM * RSTR)     // 10240
#define B_STAGE (BN * RSTR)     // 10240
#define STAGE_BYTES (A_STAGE + B_STAGE)   // 20480
#define SMEM_TOTAL (STAGES * STAGE_BYTES) // 81920 (x2 CTAs <= 228KB)

static __device__ __forceinline__ void cp16(uint32_t dst, const void* src) {
    asm volatile("cp.async.cg.shared.global [%0], [%1], 16;"
                 :: "r"(dst), "l"(src) : "memory");
}

static __device__ __forceinline__ void ldsm_a(uint32_t addr, uint32_t* r) {
    asm volatile("ldmatrix.sync.aligned.m8n8.x4.shared.b16 {%0,%1,%2,%3}, [%4];"
                 : "=r"(r[0]), "=r"(r[1]), "=r"(r[2]), "=r"(r[3]) : "r"(addr));
}

__global__ __launch_bounds__(256, 2)
void gemm_kernel(const float* __restrict__ bias,
                 const float* __restrict__ w_scale,
                 float* __restrict__ C, int M, int N, int K) {
    extern __shared__ char smem[];
    const uint32_t sbase = smem_u32(smem);
    const int tid  = threadIdx.x;
    const int warp = tid >> 5;
    const int lane = tid & 31;
    const int wm   = warp >> 1;   // 0..3: 32-row warp tile
    const int wn   = warp & 1;    // 0..1: 64-col warp tile
    const int bm   = blockIdx.y * BM;
    const int bn   = blockIdx.x * BN;
    const int NCHUNK = K / BKB;   // 64

    // ---- precomputed global source cursors (2 vec16 per tile per thread) ----
    const int lrow = tid >> 2;            // 0..63
    const int lc16 = (tid & 3) * 16;      // 0..48
    const uint8_t* asrc = g_qx + (size_t)(bm + lrow) * K + lc16;
    const uint8_t* bsrc = g_qw + (size_t)(bn + lrow) * K + lc16;
    const size_t rowskip = (size_t)64 * K;

    // ---- precomputed smem store bases (stage 0; stage adds const) ----
    const uint32_t ast = sbase + lrow * RSTR + lc16;
    const uint32_t bst = ast + A_STAGE;

    // ---- precomputed fragment base addresses (stage 0, kstep 0) ----
    uint32_t afb[2];
#pragma unroll
    for (int mt = 0; mt < 2; mt++)
        afb[mt] = sbase + (wm * 32 + mt * 16 + (lane & 15)) * RSTR
                + (lane >> 4) * 16;
    uint32_t bfb[4];
#pragma unroll
    for (int p = 0; p < 4; p++)
        bfb[p] = sbase + A_STAGE
               + (wn * 64 + p * 16 + ((lane >> 4) << 3) + (lane & 7)) * RSTR
               + ((lane >> 3) & 1) * 16;

    float acc[2][8][4];
#pragma unroll
    for (int a = 0; a < 2; a++)
#pragma unroll
        for (int b = 0; b < 8; b++)
#pragma unroll
            for (int c = 0; c < 4; c++) acc[a][b][c] = 0.0f;

    // prologue: fill stages 0..2
#pragma unroll
    for (int s = 0; s < STAGES - 1; s++) {
        cp16(ast + s * STAGE_BYTES,             asrc + s * BKB);
        cp16(ast + s * STAGE_BYTES + 64 * RSTR, asrc + rowskip + s * BKB);
        cp16(bst + s * STAGE_BYTES,             bsrc + s * BKB);
        cp16(bst + s * STAGE_BYTES + 64 * RSTR, bsrc + rowskip + s * BKB);
        asm volatile("cp.async.commit_group;" ::: "memory");
    }

    int kpref = (STAGES - 1) * BKB;   // byte offset of next chunk to prefetch

#pragma unroll 1
    for (int it = 0; it < NCHUNK; it += STAGES) {
#pragma unroll
        for (int s = 0; s < STAGES; s++) {    // s is compile-time
            asm volatile("cp.async.wait_group %0;" :: "n"(STAGES - 2) : "memory");
            __syncthreads();

            uint32_t af[2][4];
            uint32_t bf[8][2];
            // kstep 0 fragments (LDSM latency hides under cp.async issue below)
#pragma unroll
            for (int mt = 0; mt < 2; mt++)
                ldsm_a(afb[mt] + s * STAGE_BYTES, af[mt]);
#pragma unroll
            for (int p = 0; p < 4; p++) {
                uint32_t r[4];
                ldsm_a(bfb[p] + s * STAGE_BYTES, r);
                bf[2 * p + 0][0] = r[0]; bf[2 * p + 0][1] = r[1];
                bf[2 * p + 1][0] = r[2]; bf[2 * p + 1][1] = r[3];
            }

            // prefetch chunk into the stage just freed (compile-time index)
            if (kpref < K) {
                const int ps = (s + STAGES - 1) % STAGES;   // compile-time
                cp16(ast + ps * STAGE_BYTES,             asrc + kpref);
                cp16(ast + ps * STAGE_BYTES + 64 * RSTR, asrc + rowskip + kpref);
                cp16(bst + ps * STAGE_BYTES,             bsrc + kpref);
                cp16(bst + ps * STAGE_BYTES + 64 * RSTR, bsrc + rowskip + kpref);
            }
            kpref += BKB;
            asm volatile("cp.async.commit_group;" ::: "memory");

#pragma unroll
            for (int mt = 0; mt < 2; mt++)
#pragma unroll
                for (int nt = 0; nt < 8; nt++)
                    asm("mma.sync.aligned.m16n8k32.row.col.f32.e4m3.e4m3.f32 "
                        "{%0,%1,%2,%3}, {%4,%5,%6,%7}, {%8,%9}, {%0,%1,%2,%3};"
                        : "+f"(acc[mt][nt][0]), "+f"(acc[mt][nt][1]),
                          "+f"(acc[mt][nt][2]), "+f"(acc[mt][nt][3])
                        : "r"(af[mt][0]), "r"(af[mt][1]),
                          "r"(af[mt][2]), "r"(af[mt][3]),
                          "r"(bf[nt][0]), "r"(bf[nt][1]));

            // kstep 1 (byte offset 32 within chunk row)
#pragma unroll
            for (int mt = 0; mt < 2; mt++)
                ldsm_a(afb[mt] + s * STAGE_BYTES + 32, af[mt]);
#pragma unroll
            for (int p = 0; p < 4; p++) {
                uint32_t r[4];
                ldsm_a(bfb[p] + s * STAGE_BYTES + 32, r);
                bf[2 * p + 0][0] = r[0]; bf[2 * p + 0][1] = r[1];
                bf[2 * p + 1][0] = r[2]; bf[2 * p + 1][1] = r[3];
            }
#pragma unroll
            for (int mt = 0; mt < 2; mt++)
#pragma unroll
                for (int nt = 0; nt < 8; nt++)
                    asm("mma.sync.aligned.m16n8k32.row.col.f32.e4m3.e4m3.f32 "
                        "{%0,%1,%2,%3}, {%4,%5,%6,%7}, {%8,%9}, {%0,%1,%2,%3};"
                        : "+f"(acc[mt][nt][0]), "+f"(acc[mt][nt][1]),
                          "+f"(acc[mt][nt][2]), "+f"(acc[mt][nt][3])
                        : "r"(af[mt][0]), "r"(af[mt][1]),
                          "r"(af[mt][2]), "r"(af[mt][3]),
                          "r"(bf[nt][0]), "r"(bf[nt][1]));
        }
    }

    // epilogue: out = acc * (x_scale * w_scale) + bias
    float amax = fmaxf(__uint_as_float(g_amax_bits), 1e-12f);
    float sq = 448.0f / amax;
    float total = (1.0f / sq) * __ldg(w_scale);

#pragma unroll
    for (int mt = 0; mt < 2; mt++) {
        int r0 = bm + wm * 32 + mt * 16 + (lane >> 2);
#pragma unroll
        for (int nt = 0; nt < 8; nt++) {
            int cix = bn + wn * 64 + nt * 8 + (lane & 3) * 2;
            float b0 = __ldg(&bias[cix]);
            float b1 = __ldg(&bias[cix + 1]);
            float2 v0, v1;
            v0.x = acc[mt][nt][0] * total + b0;
            v0.y = acc[mt][nt][1] * total + b1;
            v1.x = acc[mt][nt][2] * total + b0;
            v1.y = acc[mt][nt][3] * total + b1;
            *(float2*)(C + (size_t)r0 * N + cix)       = v0;
            *(float2*)(C + (size_t)(r0 + 8) * N + cix) = v1;
        }
    }
}

// ---------------------------------------------------------------------------
extern "C" void kernel_launch(void* const* d_in, const int* in_sizes, int n_in,
                              void* d_out, int out_size) {
    const float* x       = (const float*)d_in[0];
    const float* w       = (const float*)d_in[1];
    const float* w_scale = (const float*)d_in[2];
    const float* bias    = (const float*)d_in[3];
    float* out           = (float*)d_out;

    int N = in_sizes[3];
    int K = in_sizes[1] / N;
    int M = in_sizes[0] / K;
    int nx4 = (M * K) / 4;
    int nw4 = (N * K) / 4;

    cudaFuncSetAttribute(gemm_kernel,
                         cudaFuncAttributeMaxDynamicSharedMemorySize, SMEM_TOTAL);

    init_amax_kernel<<<1, 1>>>();
    amax_kernel<<<2960, 256>>>(x, nx4);                  // 20 x 148
    quantize_both_kernel<<<3552, 256>>>(x, w, nx4, nw4); // 24 x 148

    dim3 grid(N / BN, M / BM);
    gemm_kernel<<<grid, 256, SMEM_TOTAL>>>(bias, w_scale, out, M, N, K);
}